// round 1
// baseline (speedup 1.0000x reference)
#include <cuda_runtime.h>

#define NN 100000
#define NE 1600000
#define DF 128
#define NC 64

// Scratch (allocation-free rule: __device__ globals)
__device__ float g_y[NN * NC];    // y = x @ W^T   (25.6 MB)
__device__ float g_h[NN * NC];    // scatter accumulator (25.6 MB)
__device__ float g_deg[NN];
__device__ float g_dinv[NN];

// ---------------------------------------------------------------------------
// 1) init: h = 0, deg = 1 (self loop)
// ---------------------------------------------------------------------------
__global__ void init_kernel() {
    int i = blockIdx.x * blockDim.x + threadIdx.x;
    if (i < NN * NC) g_h[i] = 0.0f;
    if (i < NN) g_deg[i] = 1.0f;
}

// ---------------------------------------------------------------------------
// 2) degree: deg[dst] += 1 per edge
// ---------------------------------------------------------------------------
__global__ void deg_kernel(const int* __restrict__ dst) {
    int e = blockIdx.x * blockDim.x + threadIdx.x;
    if (e < NE) atomicAdd(&g_deg[dst[e]], 1.0f);
}

// ---------------------------------------------------------------------------
// 3) dinv = rsqrt(deg)   (deg >= 1 always, self loop)
// ---------------------------------------------------------------------------
__global__ void dinv_kernel() {
    int i = blockIdx.x * blockDim.x + threadIdx.x;
    if (i < NN) g_dinv[i] = rsqrtf(g_deg[i]);
}

// ---------------------------------------------------------------------------
// 4) GEMM: y[N,64] = x[N,128] @ W^T  (W stored [64,128])
//    W transposed into smem as Wsm[k*64 + c] for broadcast float4 reads.
//    One thread per row, 64 fp32 accumulators.
// ---------------------------------------------------------------------------
__global__ __launch_bounds__(256) void gemm_kernel(const float* __restrict__ x,
                                                   const float* __restrict__ W) {
    __shared__ float Wsm[DF * NC];
    int t = threadIdx.x;
    for (int i = t; i < DF * NC; i += 256) {
        int c = i >> 7;      // row of W  (i = c*128 + k)
        int k = i & 127;
        Wsm[k * NC + c] = W[i];
    }
    __syncthreads();

    int row = blockIdx.x * 256 + t;
    if (row >= NN) return;

    float acc[NC];
#pragma unroll
    for (int c = 0; c < NC; c++) acc[c] = 0.0f;

    const float4* x4 = reinterpret_cast<const float4*>(x + (size_t)row * DF);
    for (int k4 = 0; k4 < DF / 4; k4++) {
        float4 xv = x4[k4];
        float xs[4] = {xv.x, xv.y, xv.z, xv.w};
#pragma unroll
        for (int j = 0; j < 4; j++) {
            const float4* w4 = reinterpret_cast<const float4*>(&Wsm[(k4 * 4 + j) * NC]);
#pragma unroll
            for (int c4 = 0; c4 < NC / 4; c4++) {
                float4 wv = w4[c4];
                acc[c4 * 4 + 0] += xs[j] * wv.x;
                acc[c4 * 4 + 1] += xs[j] * wv.y;
                acc[c4 * 4 + 2] += xs[j] * wv.z;
                acc[c4 * 4 + 3] += xs[j] * wv.w;
            }
        }
    }

    float4* y4 = reinterpret_cast<float4*>(g_y + (size_t)row * NC);
#pragma unroll
    for (int c4 = 0; c4 < NC / 4; c4++)
        y4[c4] = make_float4(acc[c4 * 4 + 0], acc[c4 * 4 + 1],
                             acc[c4 * 4 + 2], acc[c4 * 4 + 3]);
}

// ---------------------------------------------------------------------------
// 5) propagate: h[dst] += y[src] * dinv[src] * dinv[dst]
//    Half-warp per edge: 16 lanes x float4 = 64 floats.
//    Vectorized L2 reduction (red.global.add.v4.f32, sm_90+).
// ---------------------------------------------------------------------------
__global__ __launch_bounds__(256) void prop_kernel(const int* __restrict__ src,
                                                   const int* __restrict__ dst) {
    int gid = blockIdx.x * 256 + threadIdx.x;
    int e = gid >> 4;
    int chunk = gid & 15;
    if (e >= NE) return;

    int s = src[e];   // same addr across 16 lanes -> broadcast
    int d = dst[e];
    float norm = g_dinv[s] * g_dinv[d];

    const float4* y4 = reinterpret_cast<const float4*>(g_y);
    float4 v = y4[(size_t)s * 16 + chunk];

    float4* hp = reinterpret_cast<float4*>(g_h) + (size_t)d * 16 + chunk;
    asm volatile("red.global.add.v4.f32 [%0], {%1, %2, %3, %4};"
                 :: "l"(hp), "f"(v.x * norm), "f"(v.y * norm),
                    "f"(v.z * norm), "f"(v.w * norm)
                 : "memory");
}

// ---------------------------------------------------------------------------
// 6) epilogue: logits = h + y*dinv^2 + b ; out = log_softmax(logits)
//    One warp per node, 2 classes per lane, shfl reductions.
// ---------------------------------------------------------------------------
__global__ __launch_bounds__(256) void out_kernel(const float* __restrict__ b,
                                                  float* __restrict__ out) {
    int warp = (blockIdx.x * 256 + threadIdx.x) >> 5;
    int lane = threadIdx.x & 31;
    if (warp >= NN) return;
    int node = warp;

    float di = g_dinv[node];
    float selfn = di * di;

    const float2* h2 = reinterpret_cast<const float2*>(g_h) + (size_t)node * 32;
    const float2* y2 = reinterpret_cast<const float2*>(g_y) + (size_t)node * 32;
    const float2* b2 = reinterpret_cast<const float2*>(b);

    float2 hv = h2[lane];
    float2 yv = y2[lane];
    float2 bv = b2[lane];

    float l0 = hv.x + yv.x * selfn + bv.x;
    float l1 = hv.y + yv.y * selfn + bv.y;

    float m = fmaxf(l0, l1);
#pragma unroll
    for (int o = 16; o; o >>= 1) m = fmaxf(m, __shfl_xor_sync(0xffffffffu, m, o));

    float s = __expf(l0 - m) + __expf(l1 - m);
#pragma unroll
    for (int o = 16; o; o >>= 1) s += __shfl_xor_sync(0xffffffffu, s, o);

    float lse = m + __logf(s);

    float2* o2 = reinterpret_cast<float2*>(out) + (size_t)node * 32;
    o2[lane] = make_float2(l0 - lse, l1 - lse);
}

// ---------------------------------------------------------------------------
extern "C" void kernel_launch(void* const* d_in, const int* in_sizes, int n_in,
                              void* d_out, int out_size) {
    const float* x  = (const float*)d_in[0];
    const int*   ei = (const int*)d_in[1];
    const float* W  = (const float*)d_in[2];
    const float* b  = (const float*)d_in[3];
    float* out = (float*)d_out;

    const int* src = ei;        // edge_index[0]
    const int* dst = ei + NE;   // edge_index[1]

    init_kernel<<<(NN * NC + 255) / 256, 256>>>();
    deg_kernel<<<(NE + 255) / 256, 256>>>(dst);
    dinv_kernel<<<(NN + 255) / 256, 256>>>();
    gemm_kernel<<<(NN + 255) / 256, 256>>>(x, W);
    prop_kernel<<<(NE * 16 + 255) / 256, 256>>>(src, dst);
    out_kernel<<<(NN * 32 + 255) / 256, 256>>>(b, out);
}

// round 6
// speedup vs baseline: 1.3778x; 1.3778x over previous
#include <cuda_runtime.h>
#include <cstdint>

#define NN 100000
#define NE 1600000
#define DF 128
#define NC 64

// Scratch (allocation-free rule: __device__ globals)
__device__ float g_y[NN * NC];    // y' = (x @ W^T) * dinv[row]   (25.6 MB)
__device__ float g_h[NN * NC];    // scatter accumulator of y'[src] (25.6 MB)
__device__ float g_deg[NN];
__device__ float g_dinv[NN];

__device__ __forceinline__ uint32_t smem_to_u32(const void* p) {
    uint32_t a;
    asm("{ .reg .u64 t; cvta.to.shared.u64 t, %1; cvt.u32.u64 %0, t; }"
        : "=r"(a) : "l"(p));
    return a;
}

// ---------------------------------------------------------------------------
// 1) init: h = 0, deg = 1 (self loop)
// ---------------------------------------------------------------------------
__global__ void init_kernel() {
    int i = blockIdx.x * blockDim.x + threadIdx.x;
    if (i < NN * NC) g_h[i] = 0.0f;
    if (i < NN) g_deg[i] = 1.0f;
}

// 2) degree
__global__ void deg_kernel(const int* __restrict__ dst) {
    int e = blockIdx.x * blockDim.x + threadIdx.x;
    if (e < NE) atomicAdd(&g_deg[dst[e]], 1.0f);
}

// 3) dinv
__global__ void dinv_kernel() {
    int i = blockIdx.x * blockDim.x + threadIdx.x;
    if (i < NN) g_dinv[i] = rsqrtf(g_deg[i]);
}

// ---------------------------------------------------------------------------
// 4) GEMM via packed fma.rn.f32x2 (FFMA2): y'[N,64] = (x[N,128] @ W^T) * dinv
//    Thread tile: 2 rows x 32 cols -> 32 f32x2 accumulators.
//    W in smem, transposed to [k][c] so a row of 32 cols is contiguous;
//    per k: 8x ld.shared.v2.b64 (broadcast-ish) + 32 FFMA2.
// ---------------------------------------------------------------------------
__global__ __launch_bounds__(256) void gemm2_kernel(const float* __restrict__ x,
                                                    const float* __restrict__ W) {
    __shared__ float Wsm[DF * NC];   // Wsm[k*64 + c]
    int t = threadIdx.x;
    // k-major fill: consecutive threads write consecutive c -> conflict-free STS
    for (int i = t; i < DF * NC; i += 256) {
        int k = i >> 6, c = i & 63;
        Wsm[k * NC + c] = W[c * DF + k];
    }
    __syncthreads();

    int gid = blockIdx.x * 256 + t;
    int p  = gid >> 1;          // row pair
    int ch = gid & 1;           // column half (0: cols 0-31, 1: cols 32-63)
    long r0 = (long)p * 2;
    if (r0 >= NN) return;       // NN even -> r0+1 also valid

    uint32_t wbase = smem_to_u32(Wsm) + (uint32_t)ch * 128;  // 32 cols * 4B

    unsigned long long acc0[16], acc1[16];
#pragma unroll
    for (int i = 0; i < 16; i++) { acc0[i] = 0ULL; acc1[i] = 0ULL; }

    const float4* x0 = reinterpret_cast<const float4*>(x + r0 * DF);
    const float4* x1 = reinterpret_cast<const float4*>(x + (r0 + 1) * DF);

    for (int k4 = 0; k4 < DF / 4; k4++) {
        float4 a0 = x0[k4];
        float4 a1 = x1[k4];
        float s0[4] = {a0.x, a0.y, a0.z, a0.w};
        float s1[4] = {a1.x, a1.y, a1.z, a1.w};
#pragma unroll
        for (int j = 0; j < 4; j++) {
            unsigned long long b0, b1;
            asm("mov.b64 %0, {%1, %1};" : "=l"(b0) : "f"(s0[j]));
            asm("mov.b64 %0, {%1, %1};" : "=l"(b1) : "f"(s1[j]));
            uint32_t rowa = wbase + (uint32_t)(k4 * 4 + j) * (NC * 4);
#pragma unroll
            for (int q = 0; q < 8; q++) {
                unsigned long long w0, w1;
                asm("ld.shared.v2.b64 {%0, %1}, [%2];"
                    : "=l"(w0), "=l"(w1) : "r"(rowa + q * 16));
                asm("fma.rn.f32x2 %0, %1, %2, %0;" : "+l"(acc0[2*q])   : "l"(b0), "l"(w0));
                asm("fma.rn.f32x2 %0, %1, %2, %0;" : "+l"(acc0[2*q+1]) : "l"(b0), "l"(w1));
                asm("fma.rn.f32x2 %0, %1, %2, %0;" : "+l"(acc1[2*q])   : "l"(b1), "l"(w0));
                asm("fma.rn.f32x2 %0, %1, %2, %0;" : "+l"(acc1[2*q+1]) : "l"(b1), "l"(w1));
            }
        }
    }

    // scale by dinv (fold norm into y) and store
    float d0 = g_dinv[r0];
    float d1 = g_dinv[r0 + 1];
    float4* yo0 = reinterpret_cast<float4*>(g_y + r0 * NC + ch * 32);
    float4* yo1 = reinterpret_cast<float4*>(g_y + (r0 + 1) * NC + ch * 32);
#pragma unroll
    for (int i = 0; i < 8; i++) {
        float4 v0, v1;
        asm("mov.b64 {%0, %1}, %2;" : "=f"(v0.x), "=f"(v0.y) : "l"(acc0[2*i]));
        asm("mov.b64 {%0, %1}, %2;" : "=f"(v0.z), "=f"(v0.w) : "l"(acc0[2*i+1]));
        asm("mov.b64 {%0, %1}, %2;" : "=f"(v1.x), "=f"(v1.y) : "l"(acc1[2*i]));
        asm("mov.b64 {%0, %1}, %2;" : "=f"(v1.z), "=f"(v1.w) : "l"(acc1[2*i+1]));
        v0.x *= d0; v0.y *= d0; v0.z *= d0; v0.w *= d0;
        v1.x *= d1; v1.y *= d1; v1.z *= d1; v1.w *= d1;
        yo0[i] = v0;
        yo1[i] = v1;
    }
}

// ---------------------------------------------------------------------------
// 5) propagate: h[dst] += y'[src]   (norms pre-folded; pure gather-scatter)
//    Half-warp per edge: 16 lanes x float4, red.global.add.v4.f32
// ---------------------------------------------------------------------------
__global__ __launch_bounds__(256) void prop_kernel(const int* __restrict__ src,
                                                   const int* __restrict__ dst) {
    int gid = blockIdx.x * 256 + threadIdx.x;
    int e = gid >> 4;
    int chunk = gid & 15;
    if (e >= NE) return;

    int s = src[e];
    int d = dst[e];

    const float4* y4 = reinterpret_cast<const float4*>(g_y);
    float4 v = y4[(size_t)s * 16 + chunk];

    float4* hp = reinterpret_cast<float4*>(g_h) + (size_t)d * 16 + chunk;
    asm volatile("red.global.add.v4.f32 [%0], {%1, %2, %3, %4};"
                 :: "l"(hp), "f"(v.x), "f"(v.y), "f"(v.z), "f"(v.w)
                 : "memory");
}

// ---------------------------------------------------------------------------
// 6) epilogue: logits = (h' + y')*dinv + b ; out = log_softmax(logits)
//    One warp per node, 2 classes per lane, shfl reductions.
// ---------------------------------------------------------------------------
__global__ __launch_bounds__(256) void out_kernel(const float* __restrict__ b,
                                                  float* __restrict__ out) {
    int warp = (blockIdx.x * 256 + threadIdx.x) >> 5;
    int lane = threadIdx.x & 31;
    if (warp >= NN) return;
    int node = warp;

    float di = g_dinv[node];

    const float2* h2 = reinterpret_cast<const float2*>(g_h) + (size_t)node * 32;
    const float2* y2 = reinterpret_cast<const float2*>(g_y) + (size_t)node * 32;
    const float2* b2 = reinterpret_cast<const float2*>(b);

    float2 hv = h2[lane];
    float2 yv = y2[lane];
    float2 bv = b2[lane];

    float l0 = (hv.x + yv.x) * di + bv.x;
    float l1 = (hv.y + yv.y) * di + bv.y;

    float m = fmaxf(l0, l1);
#pragma unroll
    for (int o = 16; o; o >>= 1) m = fmaxf(m, __shfl_xor_sync(0xffffffffu, m, o));

    float s = __expf(l0 - m) + __expf(l1 - m);
#pragma unroll
    for (int o = 16; o; o >>= 1) s += __shfl_xor_sync(0xffffffffu, s, o);

    float lse = m + __logf(s);

    float2* o2 = reinterpret_cast<float2*>(out) + (size_t)node * 32;
    o2[lane] = make_float2(l0 - lse, l1 - lse);
}

// ---------------------------------------------------------------------------
extern "C" void kernel_launch(void* const* d_in, const int* in_sizes, int n_in,
                              void* d_out, int out_size) {
    const float* x  = (const float*)d_in[0];
    const int*   ei = (const int*)d_in[1];
    const float* W  = (const float*)d_in[2];
    const float* b  = (const float*)d_in[3];
    float* out = (float*)d_out;

    const int* src = ei;        // edge_index[0]
    const int* dst = ei + NE;   // edge_index[1]

    init_kernel<<<(NN * NC + 255) / 256, 256>>>();
    deg_kernel<<<(NE + 255) / 256, 256>>>(dst);
    dinv_kernel<<<(NN + 255) / 256, 256>>>();
    gemm2_kernel<<<(NN + 255) / 256, 256>>>(x, W);
    prop_kernel<<<(NE * 16 + 255) / 256, 256>>>(src, dst);
    out_kernel<<<(NN * 32 + 255) / 256, 256>>>(b, out);
}

// round 7
// speedup vs baseline: 1.5968x; 1.1589x over previous
#include <cuda_runtime.h>
#include <cstdint>

#define NN 100000
#define NE 1600000
#define DF 128
#define NC 64

// Scratch (allocation-free rule: __device__ globals)
__device__ float g_y[NN * NC];    // y' = (x @ W^T) * dinv[row]   (25.6 MB)
__device__ float g_h[NN * NC];    // scatter accumulator of y'[src] (25.6 MB)
__device__ float g_deg[NN];
__device__ float g_dinv[NN];

__device__ __forceinline__ uint32_t smem_to_u32(const void* p) {
    uint32_t a;
    asm("{ .reg .u64 t; cvta.to.shared.u64 t, %1; cvt.u32.u64 %0, t; }"
        : "=r"(a) : "l"(p));
    return a;
}

// ---------------------------------------------------------------------------
// 1) init: h = 0, deg = 1 (self loop)
// ---------------------------------------------------------------------------
__global__ void init_kernel() {
    int i = blockIdx.x * blockDim.x + threadIdx.x;
    if (i < NN * NC) g_h[i] = 0.0f;
    if (i < NN) g_deg[i] = 1.0f;
}

// 2) degree
__global__ void deg_kernel(const int* __restrict__ dst) {
    int e = blockIdx.x * blockDim.x + threadIdx.x;
    if (e < NE) atomicAdd(&g_deg[dst[e]], 1.0f);
}

// 3) dinv
__global__ void dinv_kernel() {
    int i = blockIdx.x * blockDim.x + threadIdx.x;
    if (i < NN) g_dinv[i] = rsqrtf(g_deg[i]);
}

// ---------------------------------------------------------------------------
// 4) GEMM via packed fma.rn.f32x2: y'[N,64] = (x[N,128] @ W^T) * dinv
//    Thread tile: 2 rows x 32 cols -> 32 f32x2 accumulators.
//    WARP-UNIFORM W addressing: ch = warpId&1, rows by lane -> every
//    ld.shared.v2.b64 is a pure 32-lane broadcast (1 phase, no conflicts).
//    k-loop unrolled x4 so ptxas batches 8 LDG.128 (MLP=8).
// ---------------------------------------------------------------------------
__global__ __launch_bounds__(256) void gemm2_kernel(const float* __restrict__ x,
                                                    const float* __restrict__ W) {
    __shared__ float Wsm[DF * NC];   // Wsm[k*64 + c]
    int t = threadIdx.x;
    for (int i = t; i < DF * NC; i += 256) {
        int k = i >> 6, c = i & 63;
        Wsm[k * NC + c] = W[c * DF + k];
    }
    __syncthreads();

    int w = t >> 5, l = t & 31;
    int ch = w & 1;                              // warp-uniform column half
    int p = blockIdx.x * 128 + (w >> 1) * 32 + l; // row pair, lane-distinct
    long r0 = (long)p * 2;
    if (r0 >= NN) return;                        // NN even -> r0+1 also valid

    uint32_t wbase = smem_to_u32(Wsm) + (uint32_t)ch * 128;  // uniform per warp

    unsigned long long acc0[16], acc1[16];
#pragma unroll
    for (int i = 0; i < 16; i++) { acc0[i] = 0ULL; acc1[i] = 0ULL; }

    const float4* x0 = reinterpret_cast<const float4*>(x + r0 * DF);
    const float4* x1 = reinterpret_cast<const float4*>(x + (r0 + 1) * DF);

#pragma unroll 4
    for (int k4 = 0; k4 < DF / 4; k4++) {
        float4 a0 = x0[k4];
        float4 a1 = x1[k4];
        float s0[4] = {a0.x, a0.y, a0.z, a0.w};
        float s1[4] = {a1.x, a1.y, a1.z, a1.w};
#pragma unroll
        for (int j = 0; j < 4; j++) {
            unsigned long long b0, b1;
            asm("mov.b64 %0, {%1, %1};" : "=l"(b0) : "f"(s0[j]));
            asm("mov.b64 %0, {%1, %1};" : "=l"(b1) : "f"(s1[j]));
            uint32_t rowa = wbase + (uint32_t)(k4 * 4 + j) * (NC * 4);
#pragma unroll
            for (int q = 0; q < 8; q++) {
                unsigned long long w0, w1;
                asm("ld.shared.v2.b64 {%0, %1}, [%2];"
                    : "=l"(w0), "=l"(w1) : "r"(rowa + q * 16));
                asm("fma.rn.f32x2 %0, %1, %2, %0;" : "+l"(acc0[2*q])   : "l"(b0), "l"(w0));
                asm("fma.rn.f32x2 %0, %1, %2, %0;" : "+l"(acc0[2*q+1]) : "l"(b0), "l"(w1));
                asm("fma.rn.f32x2 %0, %1, %2, %0;" : "+l"(acc1[2*q])   : "l"(b1), "l"(w0));
                asm("fma.rn.f32x2 %0, %1, %2, %0;" : "+l"(acc1[2*q+1]) : "l"(b1), "l"(w1));
            }
        }
    }

    // scale by dinv (fold norm into y) and store
    float d0 = g_dinv[r0];
    float d1 = g_dinv[r0 + 1];
    float4* yo0 = reinterpret_cast<float4*>(g_y + r0 * NC + ch * 32);
    float4* yo1 = reinterpret_cast<float4*>(g_y + (r0 + 1) * NC + ch * 32);
#pragma unroll
    for (int i = 0; i < 8; i++) {
        float4 v0, v1;
        asm("mov.b64 {%0, %1}, %2;" : "=f"(v0.x), "=f"(v0.y) : "l"(acc0[2*i]));
        asm("mov.b64 {%0, %1}, %2;" : "=f"(v0.z), "=f"(v0.w) : "l"(acc0[2*i+1]));
        asm("mov.b64 {%0, %1}, %2;" : "=f"(v1.x), "=f"(v1.y) : "l"(acc1[2*i]));
        asm("mov.b64 {%0, %1}, %2;" : "=f"(v1.z), "=f"(v1.w) : "l"(acc1[2*i+1]));
        v0.x *= d0; v0.y *= d0; v0.z *= d0; v0.w *= d0;
        v1.x *= d1; v1.y *= d1; v1.z *= d1; v1.w *= d1;
        yo0[i] = v0;
        yo1[i] = v1;
    }
}

// ---------------------------------------------------------------------------
// 5) propagate: h[dst] += y'[src]   (norms pre-folded; pure gather-scatter)
//    Half-warp per edge: 16 lanes x float4, red.global.add.v4.f32
// ---------------------------------------------------------------------------
__global__ __launch_bounds__(256) void prop_kernel(const int* __restrict__ src,
                                                   const int* __restrict__ dst) {
    int gid = blockIdx.x * 256 + threadIdx.x;
    int e = gid >> 4;
    int chunk = gid & 15;
    if (e >= NE) return;

    int s = src[e];
    int d = dst[e];

    const float4* y4 = reinterpret_cast<const float4*>(g_y);
    float4 v = y4[(size_t)s * 16 + chunk];

    float4* hp = reinterpret_cast<float4*>(g_h) + (size_t)d * 16 + chunk;
    asm volatile("red.global.add.v4.f32 [%0], {%1, %2, %3, %4};"
                 :: "l"(hp), "f"(v.x), "f"(v.y), "f"(v.z), "f"(v.w)
                 : "memory");
}

// ---------------------------------------------------------------------------
// 6) epilogue: logits = (h' + y')*dinv + b ; out = log_softmax(logits)
// ---------------------------------------------------------------------------
__global__ __launch_bounds__(256) void out_kernel(const float* __restrict__ b,
                                                  float* __restrict__ out) {
    int warp = (blockIdx.x * 256 + threadIdx.x) >> 5;
    int lane = threadIdx.x & 31;
    if (warp >= NN) return;
    int node = warp;

    float di = g_dinv[node];

    const float2* h2 = reinterpret_cast<const float2*>(g_h) + (size_t)node * 32;
    const float2* y2 = reinterpret_cast<const float2*>(g_y) + (size_t)node * 32;
    const float2* b2 = reinterpret_cast<const float2*>(b);

    float2 hv = h2[lane];
    float2 yv = y2[lane];
    float2 bv = b2[lane];

    float l0 = (hv.x + yv.x) * di + bv.x;
    float l1 = (hv.y + yv.y) * di + bv.y;

    float m = fmaxf(l0, l1);
#pragma unroll
    for (int o = 16; o; o >>= 1) m = fmaxf(m, __shfl_xor_sync(0xffffffffu, m, o));

    float s = __expf(l0 - m) + __expf(l1 - m);
#pragma unroll
    for (int o = 16; o; o >>= 1) s += __shfl_xor_sync(0xffffffffu, s, o);

    float lse = m + __logf(s);

    float2* o2 = reinterpret_cast<float2*>(out) + (size_t)node * 32;
    o2[lane] = make_float2(l0 - lse, l1 - lse);
}

// ---------------------------------------------------------------------------
extern "C" void kernel_launch(void* const* d_in, const int* in_sizes, int n_in,
                              void* d_out, int out_size) {
    const float* x  = (const float*)d_in[0];
    const int*   ei = (const int*)d_in[1];
    const float* W  = (const float*)d_in[2];
    const float* b  = (const float*)d_in[3];
    float* out = (float*)d_out;

    const int* src = ei;        // edge_index[0]
    const int* dst = ei + NE;   // edge_index[1]

    init_kernel<<<(NN * NC + 255) / 256, 256>>>();
    deg_kernel<<<(NE + 255) / 256, 256>>>(dst);
    dinv_kernel<<<(NN + 255) / 256, 256>>>();
    gemm2_kernel<<<(NN + 255) / 256, 256>>>(x, W);
    prop_kernel<<<(NE * 16 + 255) / 256, 256>>>(src, dst);
    out_kernel<<<(NN * 32 + 255) / 256, 256>>>(b, out);
}

// round 8
// speedup vs baseline: 2.0894x; 1.3085x over previous
#include <cuda_runtime.h>
#include <cstdint>

#define NN 100000
#define NE 1600000
#define DF 128
#define NC 64
#define SCAN_BLK 98   // ceil(100000/1024)

// Scratch (__device__ globals per allocation-free rule)
__device__ float g_y[NN * NC];      // y' = (x @ W^T) * dinv[row]  (25.6MB)
__device__ float g_dinv[NN];
__device__ int   g_cnt[NN];         // edge-dst histogram (deg - 1)
__device__ int   g_incl[NN];        // block-local inclusive scan
__device__ int   g_bsum[128];       // per-block sums
__device__ int   g_bscan[128];      // scanned block sums
__device__ int   g_rowstart[NN];    // CSR row pointer (exclusive prefix)
__device__ int   g_cursor[NN];      // scatter cursors
__device__ int   g_ssrc[NE];        // edge sources sorted by dst

__device__ __forceinline__ uint32_t smem_to_u32(const void* p) {
    uint32_t a;
    asm("{ .reg .u64 t; cvta.to.shared.u64 t, %1; cvt.u32.u64 %0, t; }"
        : "=r"(a) : "l"(p));
    return a;
}

// ---------------------------------------------------------------------------
// 1) zero histogram
// ---------------------------------------------------------------------------
__global__ void zero_kernel() {
    int i = blockIdx.x * blockDim.x + threadIdx.x;
    if (i < NN) g_cnt[i] = 0;
}

// 2) histogram over edge destinations (int atomics, spread addresses)
__global__ void hist_kernel(const int* __restrict__ dst) {
    int e = blockIdx.x * blockDim.x + threadIdx.x;
    if (e < NE) atomicAdd(&g_cnt[dst[e]], 1);
}

// 3a) block-local inclusive scan (1024/block)
__global__ __launch_bounds__(1024) void scan_a_kernel() {
    __shared__ int sh[1024];
    int t = threadIdx.x;
    int gid = blockIdx.x * 1024 + t;
    int v = (gid < NN) ? g_cnt[gid] : 0;
    sh[t] = v;
    __syncthreads();
#pragma unroll
    for (int off = 1; off < 1024; off <<= 1) {
        int u = (t >= off) ? sh[t - off] : 0;
        __syncthreads();
        sh[t] += u;
        __syncthreads();
    }
    if (gid < NN) g_incl[gid] = sh[t];
    if (t == 1023) g_bsum[blockIdx.x] = sh[t];
}

// 3b) scan the block sums (single block)
__global__ __launch_bounds__(128) void scan_b_kernel() {
    __shared__ int sh[128];
    int t = threadIdx.x;
    sh[t] = (t < SCAN_BLK) ? g_bsum[t] : 0;
    __syncthreads();
#pragma unroll
    for (int off = 1; off < 128; off <<= 1) {
        int u = (t >= off) ? sh[t - off] : 0;
        __syncthreads();
        sh[t] += u;
        __syncthreads();
    }
    g_bscan[t] = sh[t];
}

// 3c) finalize: row_start (exclusive), cursor copy, dinv = rsqrt(cnt+1)
__global__ void scan_c_kernel() {
    int gid = blockIdx.x * blockDim.x + threadIdx.x;
    if (gid >= NN) return;
    int b = gid >> 10;
    int base = (b > 0) ? g_bscan[b - 1] : 0;
    int c = g_cnt[gid];
    int rs = base + g_incl[gid] - c;
    g_rowstart[gid] = rs;
    g_cursor[gid] = rs;
    g_dinv[gid] = rsqrtf((float)c + 1.0f);
}

// 4) scatter: sort edge sources by dst bucket
__global__ void scatter_kernel(const int* __restrict__ src,
                               const int* __restrict__ dst) {
    int e = blockIdx.x * blockDim.x + threadIdx.x;
    if (e >= NE) return;
    int d = dst[e];
    int pos = atomicAdd(&g_cursor[d], 1);
    g_ssrc[pos] = src[e];
}

// ---------------------------------------------------------------------------
// 5) GEMM: y'[N,64] = (x[N,128] @ W^T) * dinv, fma.rn.f32x2
//    CTA: 128 thr, 256 rows. 4 warps: ch = w&1 (col half, warp-uniform),
//    pair = w>>1. Thread: rows pair*128 + 32*rr + lane (rr=0..3), 32 cols.
//    x staged coalesced into Xs (stride 48B -> conflict-free LDS.128 readback),
//    prefetch next chunk during compute. W broadcast from smem.
// ---------------------------------------------------------------------------
__global__ __launch_bounds__(128) void gemm3_kernel(const float* __restrict__ x,
                                                    const float* __restrict__ W) {
    __shared__ float Wsm[DF * NC];   // [k][c], 32KB
    __shared__ float Xs[256 * 12];   // 12KB: 256 rows x 8 floats @ stride 12 words
    int t = threadIdx.x;

    for (int i = t; i < DF * NC; i += 128) {
        int k = i >> 6, c = i & 63;
        Wsm[k * NC + c] = W[c * DF + k];
    }

    int w = t >> 5, l = t & 31;
    int ch = w & 1, pair = w >> 1;
    int rbase = blockIdx.x * 256;
    uint32_t w_base = smem_to_u32(Wsm) + (uint32_t)ch * 128;

    unsigned long long acc[4][16];
#pragma unroll
    for (int rr = 0; rr < 4; rr++)
#pragma unroll
        for (int q = 0; q < 16; q++) acc[rr][q] = 0ULL;

    const float4* x4 = reinterpret_cast<const float4*>(x);

    // prefetch chunk 0 (512 float4 over 128 threads)
    float4 pre[4];
#pragma unroll
    for (int i2 = 0; i2 < 4; i2++) {
        int idx = t + i2 * 128;
        int row = idx >> 1, half = idx & 1;
        int gr = rbase + row;
        pre[i2] = (gr < NN) ? x4[(size_t)gr * 32 + half]
                            : make_float4(0.f, 0.f, 0.f, 0.f);
    }

    for (int cc = 0; cc < 16; cc++) {
        // store staged chunk
#pragma unroll
        for (int i2 = 0; i2 < 4; i2++) {
            int idx = t + i2 * 128;
            int row = idx >> 1, half = idx & 1;
            *reinterpret_cast<float4*>(Xs + row * 12 + half * 4) = pre[i2];
        }
        __syncthreads();

        // prefetch next chunk
        if (cc < 15) {
#pragma unroll
            for (int i2 = 0; i2 < 4; i2++) {
                int idx = t + i2 * 128;
                int row = idx >> 1, half = idx & 1;
                int gr = rbase + row;
                pre[i2] = (gr < NN) ? x4[(size_t)gr * 32 + (cc + 1) * 2 + half]
                                    : make_float4(0.f, 0.f, 0.f, 0.f);
            }
        }

        // load this thread's 4 rows x 8 floats from Xs (conflict-free)
        float af[4][8];
#pragma unroll
        for (int rr = 0; rr < 4; rr++) {
            int rl = pair * 128 + 32 * rr + l;
            float4 v0 = *reinterpret_cast<const float4*>(Xs + rl * 12);
            float4 v1 = *reinterpret_cast<const float4*>(Xs + rl * 12 + 4);
            af[rr][0] = v0.x; af[rr][1] = v0.y; af[rr][2] = v0.z; af[rr][3] = v0.w;
            af[rr][4] = v1.x; af[rr][5] = v1.y; af[rr][6] = v1.z; af[rr][7] = v1.w;
        }

#pragma unroll
        for (int k = 0; k < 8; k++) {
            unsigned long long bm[4];
#pragma unroll
            for (int rr = 0; rr < 4; rr++)
                asm("mov.b64 %0, {%1, %1};" : "=l"(bm[rr]) : "f"(af[rr][k]));
            uint32_t rowa = w_base + (uint32_t)(cc * 8 + k) * (NC * 4);
#pragma unroll
            for (int q = 0; q < 8; q++) {
                unsigned long long w0, w1;
                asm("ld.shared.v2.b64 {%0, %1}, [%2];"
                    : "=l"(w0), "=l"(w1) : "r"(rowa + q * 16));
#pragma unroll
                for (int rr = 0; rr < 4; rr++) {
                    asm("fma.rn.f32x2 %0, %1, %2, %0;" : "+l"(acc[rr][2*q])   : "l"(bm[rr]), "l"(w0));
                    asm("fma.rn.f32x2 %0, %1, %2, %0;" : "+l"(acc[rr][2*q+1]) : "l"(bm[rr]), "l"(w1));
                }
            }
        }
        __syncthreads();
    }

    // scale by dinv and store
#pragma unroll
    for (int rr = 0; rr < 4; rr++) {
        int r = rbase + pair * 128 + 32 * rr + l;
        if (r >= NN) continue;
        float d = g_dinv[r];
        float4* yo = reinterpret_cast<float4*>(g_y + (size_t)r * NC + ch * 32);
#pragma unroll
        for (int q = 0; q < 8; q++) {
            float4 v;
            asm("mov.b64 {%0, %1}, %2;" : "=f"(v.x), "=f"(v.y) : "l"(acc[rr][2*q]));
            asm("mov.b64 {%0, %1}, %2;" : "=f"(v.z), "=f"(v.w) : "l"(acc[rr][2*q+1]));
            v.x *= d; v.y *= d; v.z *= d; v.w *= d;
            yo[q] = v;
        }
    }
}

// ---------------------------------------------------------------------------
// 6) fused gather + log_softmax: warp per node.
//    h = y'[node] + sum over CSR edges of y'[src]; two half-warps split edges;
//    shfl merge; logits = h*dinv + b; warp softmax; write out.
//    No atomics, no g_h, no separate epilogue.
// ---------------------------------------------------------------------------
__global__ __launch_bounds__(256) void gather_out_kernel(const float* __restrict__ b,
                                                         float* __restrict__ out) {
    int node = (blockIdx.x * 256 + threadIdx.x) >> 5;
    int l = threadIdx.x & 31;
    if (node >= NN) return;
    int half = l >> 4, chunk = l & 15;

    int start = g_rowstart[node];
    int n = g_cnt[node];
    const float4* y4 = reinterpret_cast<const float4*>(g_y);

    float4 acc = make_float4(0.f, 0.f, 0.f, 0.f);
    if (half == 0) acc = y4[(size_t)node * 16 + chunk];   // self loop

    for (int e = half; e < n; e += 2) {
        int s = g_ssrc[start + e];                         // broadcast per half
        float4 v = y4[(size_t)s * 16 + chunk];
        acc.x += v.x; acc.y += v.y; acc.z += v.z; acc.w += v.w;
    }

    // merge the two half-warps
    acc.x += __shfl_xor_sync(0xffffffffu, acc.x, 16);
    acc.y += __shfl_xor_sync(0xffffffffu, acc.y, 16);
    acc.z += __shfl_xor_sync(0xffffffffu, acc.z, 16);
    acc.w += __shfl_xor_sync(0xffffffffu, acc.w, 16);

    // redistribute: lane l takes logits [2l, 2l+1] from chunk l>>1
    int srcl = l >> 1;
    float4 v;
    v.x = __shfl_sync(0xffffffffu, acc.x, srcl);
    v.y = __shfl_sync(0xffffffffu, acc.y, srcl);
    v.z = __shfl_sync(0xffffffffu, acc.z, srcl);
    v.w = __shfl_sync(0xffffffffu, acc.w, srcl);
    float2 mine = (l & 1) ? make_float2(v.z, v.w) : make_float2(v.x, v.y);

    float di = g_dinv[node];
    const float2* b2 = reinterpret_cast<const float2*>(b);
    float2 bb = b2[l];
    float l0 = mine.x * di + bb.x;
    float l1 = mine.y * di + bb.y;

    float m = fmaxf(l0, l1);
#pragma unroll
    for (int o = 16; o; o >>= 1) m = fmaxf(m, __shfl_xor_sync(0xffffffffu, m, o));
    float s = __expf(l0 - m) + __expf(l1 - m);
#pragma unroll
    for (int o = 16; o; o >>= 1) s += __shfl_xor_sync(0xffffffffu, s, o);
    float lse = m + __logf(s);

    reinterpret_cast<float2*>(out + (size_t)node * NC)[l] = make_float2(l0 - lse, l1 - lse);
}

// ---------------------------------------------------------------------------
extern "C" void kernel_launch(void* const* d_in, const int* in_sizes, int n_in,
                              void* d_out, int out_size) {
    const float* x  = (const float*)d_in[0];
    const int*   ei = (const int*)d_in[1];
    const float* W  = (const float*)d_in[2];
    const float* b  = (const float*)d_in[3];
    float* out = (float*)d_out;

    const int* src = ei;        // edge_index[0]
    const int* dst = ei + NE;   // edge_index[1]

    zero_kernel<<<(NN + 255) / 256, 256>>>();
    hist_kernel<<<(NE + 255) / 256, 256>>>(dst);
    scan_a_kernel<<<SCAN_BLK, 1024>>>();
    scan_b_kernel<<<1, 128>>>();
    scan_c_kernel<<<(NN + 255) / 256, 256>>>();
    scatter_kernel<<<(NE + 255) / 256, 256>>>(src, dst);
    gemm3_kernel<<<(NN + 255) / 256, 128>>>(x, W);
    gather_out_kernel<<<(NN * 32 + 255) / 256, 256>>>(b, out);
}

// round 9
// speedup vs baseline: 2.3038x; 1.1026x over previous
#include <cuda_runtime.h>
#include <cstdint>

#define NN 100000
#define NE 1600000
#define DF 128
#define NC 64
#define SCAN_BLK 98   // ceil(100000/1024)

// Scratch (__device__ globals per allocation-free rule)
__device__ float g_y[NN * NC];      // y = x @ W^T  (25.6MB), NO dinv folded
__device__ float g_dinv[NN];
__device__ int   g_cnt[NN];         // edge-dst histogram (deg - 1)
__device__ int   g_incl[NN];        // block-local inclusive scan
__device__ int   g_bsum[128];       // per-block sums
__device__ int   g_bscan[128];      // scanned block sums
__device__ int   g_rowstart[NN];    // CSR row pointer (exclusive prefix)
__device__ int   g_cursor[NN];      // scatter cursors
__device__ int   g_ssrc[NE];        // edge sources sorted by dst

// Stream/event for fork-join graph parallelism (created before any capture)
static cudaStream_t g_side;
static cudaEvent_t g_evFork, g_evJoin;
namespace {
struct _Init {
    _Init() {
        cudaStreamCreateWithFlags(&g_side, cudaStreamNonBlocking);
        cudaEventCreateWithFlags(&g_evFork, cudaEventDisableTiming);
        cudaEventCreateWithFlags(&g_evJoin, cudaEventDisableTiming);
    }
};
_Init _init;
}

__device__ __forceinline__ uint32_t smem_to_u32(const void* p) {
    uint32_t a;
    asm("{ .reg .u64 t; cvta.to.shared.u64 t, %1; cvt.u32.u64 %0, t; }"
        : "=r"(a) : "l"(p));
    return a;
}

// ---------------------------------------------------------------------------
// 1) zero histogram
// ---------------------------------------------------------------------------
__global__ void zero_kernel() {
    int i = blockIdx.x * blockDim.x + threadIdx.x;
    if (i < NN) g_cnt[i] = 0;
}

// 2) histogram over edge destinations
__global__ void hist_kernel(const int* __restrict__ dst) {
    int e = blockIdx.x * blockDim.x + threadIdx.x;
    if (e < NE) atomicAdd(&g_cnt[dst[e]], 1);
}

// 3a) block inclusive scan, warp-shfl based (1024/block)
__global__ __launch_bounds__(1024) void scan_a_kernel() {
    __shared__ int wsum[32];
    int t = threadIdx.x;
    int lane = t & 31, wid = t >> 5;
    int gid = blockIdx.x * 1024 + t;
    int inc = (gid < NN) ? g_cnt[gid] : 0;
#pragma unroll
    for (int off = 1; off < 32; off <<= 1) {
        int u = __shfl_up_sync(0xffffffffu, inc, off);
        if (lane >= off) inc += u;
    }
    if (lane == 31) wsum[wid] = inc;
    __syncthreads();
    if (wid == 0) {
        int s2 = wsum[lane];
#pragma unroll
        for (int off = 1; off < 32; off <<= 1) {
            int u = __shfl_up_sync(0xffffffffu, s2, off);
            if (lane >= off) s2 += u;
        }
        wsum[lane] = s2;
    }
    __syncthreads();
    if (wid > 0) inc += wsum[wid - 1];
    if (gid < NN) g_incl[gid] = inc;
    if (t == 1023) g_bsum[blockIdx.x] = inc;
}

// 3b) scan the 98 block sums (single block, 128 thr)
__global__ __launch_bounds__(128) void scan_b_kernel() {
    __shared__ int wsum[4];
    int t = threadIdx.x;
    int lane = t & 31, wid = t >> 5;
    int inc = (t < SCAN_BLK) ? g_bsum[t] : 0;
#pragma unroll
    for (int off = 1; off < 32; off <<= 1) {
        int u = __shfl_up_sync(0xffffffffu, inc, off);
        if (lane >= off) inc += u;
    }
    if (lane == 31) wsum[wid] = inc;
    __syncthreads();
    int add = 0;
#pragma unroll
    for (int q = 0; q < 4; q++) if (q < wid) add += wsum[q];
    g_bscan[t] = inc + add;
}

// 3c) finalize: row_start, cursor, dinv = rsqrt(cnt+1)
__global__ void scan_c_kernel() {
    int gid = blockIdx.x * blockDim.x + threadIdx.x;
    if (gid >= NN) return;
    int bl = gid >> 10;
    int base = (bl > 0) ? g_bscan[bl - 1] : 0;
    int c = g_cnt[gid];
    int rs = base + g_incl[gid] - c;
    g_rowstart[gid] = rs;
    g_cursor[gid] = rs;
    g_dinv[gid] = rsqrtf((float)c + 1.0f);
}

// 4) scatter: sort edge sources by dst bucket
__global__ void scatter_kernel(const int* __restrict__ src,
                               const int* __restrict__ dst) {
    int e = blockIdx.x * blockDim.x + threadIdx.x;
    if (e >= NE) return;
    int d = dst[e];
    int pos = atomicAdd(&g_cursor[d], 1);
    g_ssrc[pos] = src[e];
}

// ---------------------------------------------------------------------------
// 5) GEMM: y[N,64] = x[N,128] @ W^T   (fma.rn.f32x2, no dinv dependency)
// ---------------------------------------------------------------------------
__global__ __launch_bounds__(128) void gemm3_kernel(const float* __restrict__ x,
                                                    const float* __restrict__ W) {
    __shared__ float Wsm[DF * NC];   // [k][c], 32KB
    __shared__ float Xs[256 * 12];   // 12KB staged x
    int t = threadIdx.x;

    for (int i = t; i < DF * NC; i += 128) {
        int k = i >> 6, c = i & 63;
        Wsm[k * NC + c] = W[c * DF + k];
    }

    int w = t >> 5, l = t & 31;
    int ch = w & 1, pair = w >> 1;
    int rbase = blockIdx.x * 256;
    uint32_t w_base = smem_to_u32(Wsm) + (uint32_t)ch * 128;

    unsigned long long acc[4][16];
#pragma unroll
    for (int rr = 0; rr < 4; rr++)
#pragma unroll
        for (int q = 0; q < 16; q++) acc[rr][q] = 0ULL;

    const float4* x4 = reinterpret_cast<const float4*>(x);

    float4 pre[4];
#pragma unroll
    for (int i2 = 0; i2 < 4; i2++) {
        int idx = t + i2 * 128;
        int row = idx >> 1, half = idx & 1;
        int gr = rbase + row;
        pre[i2] = (gr < NN) ? x4[(size_t)gr * 32 + half]
                            : make_float4(0.f, 0.f, 0.f, 0.f);
    }

    for (int cc = 0; cc < 16; cc++) {
#pragma unroll
        for (int i2 = 0; i2 < 4; i2++) {
            int idx = t + i2 * 128;
            int row = idx >> 1, half = idx & 1;
            *reinterpret_cast<float4*>(Xs + row * 12 + half * 4) = pre[i2];
        }
        __syncthreads();

        if (cc < 15) {
#pragma unroll
            for (int i2 = 0; i2 < 4; i2++) {
                int idx = t + i2 * 128;
                int row = idx >> 1, half = idx & 1;
                int gr = rbase + row;
                pre[i2] = (gr < NN) ? x4[(size_t)gr * 32 + (cc + 1) * 2 + half]
                                    : make_float4(0.f, 0.f, 0.f, 0.f);
            }
        }

        float af[4][8];
#pragma unroll
        for (int rr = 0; rr < 4; rr++) {
            int rl = pair * 128 + 32 * rr + l;
            float4 v0 = *reinterpret_cast<const float4*>(Xs + rl * 12);
            float4 v1 = *reinterpret_cast<const float4*>(Xs + rl * 12 + 4);
            af[rr][0] = v0.x; af[rr][1] = v0.y; af[rr][2] = v0.z; af[rr][3] = v0.w;
            af[rr][4] = v1.x; af[rr][5] = v1.y; af[rr][6] = v1.z; af[rr][7] = v1.w;
        }

#pragma unroll
        for (int k = 0; k < 8; k++) {
            unsigned long long bm[4];
#pragma unroll
            for (int rr = 0; rr < 4; rr++)
                asm("mov.b64 %0, {%1, %1};" : "=l"(bm[rr]) : "f"(af[rr][k]));
            uint32_t rowa = w_base + (uint32_t)(cc * 8 + k) * (NC * 4);
#pragma unroll
            for (int q = 0; q < 8; q++) {
                unsigned long long w0, w1;
                asm("ld.shared.v2.b64 {%0, %1}, [%2];"
                    : "=l"(w0), "=l"(w1) : "r"(rowa + q * 16));
#pragma unroll
                for (int rr = 0; rr < 4; rr++) {
                    asm("fma.rn.f32x2 %0, %1, %2, %0;" : "+l"(acc[rr][2*q])   : "l"(bm[rr]), "l"(w0));
                    asm("fma.rn.f32x2 %0, %1, %2, %0;" : "+l"(acc[rr][2*q+1]) : "l"(bm[rr]), "l"(w1));
                }
            }
        }
        __syncthreads();
    }

#pragma unroll
    for (int rr = 0; rr < 4; rr++) {
        int r = rbase + pair * 128 + 32 * rr + l;
        if (r >= NN) continue;
        float4* yo = reinterpret_cast<float4*>(g_y + (size_t)r * NC + ch * 32);
#pragma unroll
        for (int q = 0; q < 8; q++) {
            float4 v;
            asm("mov.b64 {%0, %1}, %2;" : "=f"(v.x), "=f"(v.y) : "l"(acc[rr][2*q]));
            asm("mov.b64 {%0, %1}, %2;" : "=f"(v.z), "=f"(v.w) : "l"(acc[rr][2*q+1]));
            yo[q] = v;
        }
    }
}

// ---------------------------------------------------------------------------
// 6) fused gather + log_softmax, warp per node, high-MLP:
//    prefetch 32 src idx + dinv coalesced, shfl-broadcast, independent gathers.
//    acc = y[node]*dinv[node] + sum y[s]*dinv[s]; logits = acc*dinv[node] + b.
// ---------------------------------------------------------------------------
__global__ __launch_bounds__(256) void gather_out_kernel(const float* __restrict__ b,
                                                         float* __restrict__ out) {
    int node = (blockIdx.x * 256 + threadIdx.x) >> 5;
    int l = threadIdx.x & 31;
    if (node >= NN) return;
    int half = l >> 4, chunk = l & 15;

    int start = g_rowstart[node];
    int n = g_cnt[node];
    float di = g_dinv[node];
    const float4* y4 = reinterpret_cast<const float4*>(g_y);

    float4 acc = make_float4(0.f, 0.f, 0.f, 0.f);
    if (half == 0) {   // self loop: y[node] * dinv[node]
        float4 v = y4[(size_t)node * 16 + chunk];
        acc.x = v.x * di; acc.y = v.y * di; acc.z = v.z * di; acc.w = v.w * di;
    }

    for (int base = 0; base < n; base += 32) {
        int idx = base + l;
        int s = 0; float dv = 0.f;
        if (idx < n) { s = g_ssrc[start + idx]; dv = g_dinv[s]; }  // coalesced + gather
        int m = n - base; if (m > 32) m = 32;
        int jmax = (m + 1) >> 1;
        for (int j = 0; j < jmax; j++) {
            int myj = 2 * j + half;                    // even edges -> half0, odd -> half1
            int sj = __shfl_sync(0xffffffffu, s, myj);
            float dj = __shfl_sync(0xffffffffu, dv, myj);
            if (myj < m) {
                float4 v = y4[(size_t)sj * 16 + chunk];
                acc.x += v.x * dj; acc.y += v.y * dj;
                acc.z += v.z * dj; acc.w += v.w * dj;
            }
        }
    }

    // merge half-warps
    acc.x += __shfl_xor_sync(0xffffffffu, acc.x, 16);
    acc.y += __shfl_xor_sync(0xffffffffu, acc.y, 16);
    acc.z += __shfl_xor_sync(0xffffffffu, acc.z, 16);
    acc.w += __shfl_xor_sync(0xffffffffu, acc.w, 16);

    // redistribute: lane l takes logits [2l, 2l+1] from chunk l>>1
    int srcl = l >> 1;
    float4 v;
    v.x = __shfl_sync(0xffffffffu, acc.x, srcl);
    v.y = __shfl_sync(0xffffffffu, acc.y, srcl);
    v.z = __shfl_sync(0xffffffffu, acc.z, srcl);
    v.w = __shfl_sync(0xffffffffu, acc.w, srcl);
    float2 mine = (l & 1) ? make_float2(v.z, v.w) : make_float2(v.x, v.y);

    const float2* b2 = reinterpret_cast<const float2*>(b);
    float2 bb = b2[l];
    float l0 = mine.x * di + bb.x;
    float l1 = mine.y * di + bb.y;

    float m = fmaxf(l0, l1);
#pragma unroll
    for (int o = 16; o; o >>= 1) m = fmaxf(m, __shfl_xor_sync(0xffffffffu, m, o));
    float s = __expf(l0 - m) + __expf(l1 - m);
#pragma unroll
    for (int o = 16; o; o >>= 1) s += __shfl_xor_sync(0xffffffffu, s, o);
    float lse = m + __logf(s);

    reinterpret_cast<float2*>(out + (size_t)node * NC)[l] = make_float2(l0 - lse, l1 - lse);
}

// ---------------------------------------------------------------------------
extern "C" void kernel_launch(void* const* d_in, const int* in_sizes, int n_in,
                              void* d_out, int out_size) {
    const float* x  = (const float*)d_in[0];
    const int*   ei = (const int*)d_in[1];
    const float* W  = (const float*)d_in[2];
    const float* b  = (const float*)d_in[3];
    float* out = (float*)d_out;

    const int* src = ei;        // edge_index[0]
    const int* dst = ei + NE;   // edge_index[1]

    // Fork: gemm on side stream (independent of edge chain)
    cudaEventRecord(g_evFork, 0);
    cudaStreamWaitEvent(g_side, g_evFork, 0);
    gemm3_kernel<<<(NN + 255) / 256, 128, 0, g_side>>>(x, W);
    cudaEventRecord(g_evJoin, g_side);

    // Edge chain on main stream
    zero_kernel<<<(NN + 255) / 256, 256>>>();
    hist_kernel<<<(NE + 255) / 256, 256>>>(dst);
    scan_a_kernel<<<SCAN_BLK, 1024>>>();
    scan_b_kernel<<<1, 128>>>();
    scan_c_kernel<<<(NN + 255) / 256, 256>>>();
    scatter_kernel<<<(NE + 255) / 256, 256>>>(src, dst);

    // Join, then fused gather + softmax
    cudaStreamWaitEvent(0, g_evJoin, 0);
    gather_out_kernel<<<(NN * 32 + 255) / 256, 256>>>(b, out);
}

// round 13
// speedup vs baseline: 2.5062x; 1.0878x over previous
#include <cuda_runtime.h>
#include <cuda_fp16.h>
#include <cstdint>

#define NN 100000
#define NE 1600000
#define DF 128
#define NC 64
#define SCAN_BLK 98   // ceil(100000/1024)

// Scratch (__device__ globals per allocation-free rule)
__device__ __half g_yh[NN * NC];    // y = x @ W^T in fp16 (12.8MB)
__device__ float g_dinv[NN];
__device__ int   g_cnt[NN];         // edge-dst histogram (deg - 1)
__device__ int   g_incl[NN];        // inclusive scan within 1024-chunk
__device__ int   g_bsum[128];       // per-chunk sums
__device__ int   g_rowstart[NN];    // CSR row pointer (exclusive prefix)
__device__ int   g_cursor[NN];      // scatter cursors
__device__ int   g_ssrc[NE];        // edge sources sorted by dst

// Stream/events for fork-join graph parallelism. Created lazily on the FIRST
// kernel_launch call (the harness's correctness run, which precedes graph
// capture) — avoids CUDA calls in static initializers.
static cudaStream_t g_side = nullptr;
static cudaEvent_t g_evFork = nullptr, g_evJoin = nullptr;

__device__ __forceinline__ uint32_t smem_to_u32(const void* p) {
    uint32_t a;
    asm("{ .reg .u64 t; cvta.to.shared.u64 t, %1; cvt.u32.u64 %0, t; }"
        : "=r"(a) : "l"(p));
    return a;
}

__device__ __forceinline__ uint32_t h2_to_u32(__half2 h) {
    return *reinterpret_cast<uint32_t*>(&h);
}
__device__ __forceinline__ __half2 u32_to_h2(uint32_t u) {
    return *reinterpret_cast<__half2*>(&u);
}

// ---------------------------------------------------------------------------
// 1) zero histogram
// ---------------------------------------------------------------------------
__global__ void zero_kernel() {
    int i = blockIdx.x * blockDim.x + threadIdx.x;
    if (i < NN) g_cnt[i] = 0;
}

// 2) histogram over edge destinations
__global__ void hist_kernel(const int* __restrict__ dst) {
    int e = blockIdx.x * blockDim.x + threadIdx.x;
    if (e < NE) atomicAdd(&g_cnt[dst[e]], 1);
}

// 3a) inclusive scan within each 1024-chunk (warp-shfl)
__global__ __launch_bounds__(1024) void scan_a_kernel() {
    __shared__ int wsum[32];
    int t = threadIdx.x;
    int lane = t & 31, wid = t >> 5;
    int gid = blockIdx.x * 1024 + t;
    int inc = (gid < NN) ? g_cnt[gid] : 0;
#pragma unroll
    for (int off = 1; off < 32; off <<= 1) {
        int u = __shfl_up_sync(0xffffffffu, inc, off);
        if (lane >= off) inc += u;
    }
    if (lane == 31) wsum[wid] = inc;
    __syncthreads();
    if (wid == 0) {
        int s2 = wsum[lane];
#pragma unroll
        for (int off = 1; off < 32; off <<= 1) {
            int u = __shfl_up_sync(0xffffffffu, s2, off);
            if (lane >= off) s2 += u;
        }
        wsum[lane] = s2;
    }
    __syncthreads();
    if (wid > 0) inc += wsum[wid - 1];
    if (gid < NN) g_incl[gid] = inc;
    if (t == 1023) g_bsum[blockIdx.x] = inc;
}

// 3b) finalize (fused chunk-sum prefix): row_start, cursor, dinv
__global__ __launch_bounds__(256) void scan_c_kernel() {
    __shared__ int sbase;
    int t = threadIdx.x;
    int bl = blockIdx.x >> 2;
    if (t < 32) {
        int acc = 0;
        for (int q = t; q < bl; q += 32) acc += g_bsum[q];
#pragma unroll
        for (int o = 16; o; o >>= 1) acc += __shfl_xor_sync(0xffffffffu, acc, o);
        if (t == 0) sbase = acc;
    }
    __syncthreads();
    int gid = blockIdx.x * 256 + t;
    if (gid >= NN) return;
    int c = g_cnt[gid];
    int rs = sbase + g_incl[gid] - c;
    g_rowstart[gid] = rs;
    g_cursor[gid] = rs;
    g_dinv[gid] = rsqrtf((float)c + 1.0f);
}

// 4) scatter: sort edge sources by dst bucket
__global__ void scatter_kernel(const int* __restrict__ src,
                               const int* __restrict__ dst) {
    int e = blockIdx.x * blockDim.x + threadIdx.x;
    if (e >= NE) return;
    int d = dst[e];
    int pos = atomicAdd(&g_cursor[d], 1);
    g_ssrc[pos] = src[e];
}

// ---------------------------------------------------------------------------
// 5) GEMM: y[N,64] = x[N,128] @ W^T  (fma.rn.f32x2), epilogue converts to fp16
// ---------------------------------------------------------------------------
__global__ __launch_bounds__(128) void gemm3_kernel(const float* __restrict__ x,
                                                    const float* __restrict__ W) {
    __shared__ float Wsm[DF * NC];   // [k][c], 32KB
    __shared__ float Xs[256 * 12];   // 12KB staged x
    int t = threadIdx.x;

    for (int i = t; i < DF * NC; i += 128) {
        int k = i >> 6, c = i & 63;
        Wsm[k * NC + c] = W[c * DF + k];
    }

    int w = t >> 5, l = t & 31;
    int ch = w & 1, pair = w >> 1;
    int rbase = blockIdx.x * 256;
    uint32_t w_base = smem_to_u32(Wsm) + (uint32_t)ch * 128;

    unsigned long long acc[4][16];
#pragma unroll
    for (int rr = 0; rr < 4; rr++)
#pragma unroll
        for (int q = 0; q < 16; q++) acc[rr][q] = 0ULL;

    const float4* x4 = reinterpret_cast<const float4*>(x);

    float4 pre[4];
#pragma unroll
    for (int i2 = 0; i2 < 4; i2++) {
        int idx = t + i2 * 128;
        int row = idx >> 1, half = idx & 1;
        int gr = rbase + row;
        pre[i2] = (gr < NN) ? x4[(size_t)gr * 32 + half]
                            : make_float4(0.f, 0.f, 0.f, 0.f);
    }

    for (int cc = 0; cc < 16; cc++) {
#pragma unroll
        for (int i2 = 0; i2 < 4; i2++) {
            int idx = t + i2 * 128;
            int row = idx >> 1, half = idx & 1;
            *reinterpret_cast<float4*>(Xs + row * 12 + half * 4) = pre[i2];
        }
        __syncthreads();

        if (cc < 15) {
#pragma unroll
            for (int i2 = 0; i2 < 4; i2++) {
                int idx = t + i2 * 128;
                int row = idx >> 1, half = idx & 1;
                int gr = rbase + row;
                pre[i2] = (gr < NN) ? x4[(size_t)gr * 32 + (cc + 1) * 2 + half]
                                    : make_float4(0.f, 0.f, 0.f, 0.f);
            }
        }

        float af[4][8];
#pragma unroll
        for (int rr = 0; rr < 4; rr++) {
            int rl = pair * 128 + 32 * rr + l;
            float4 v0 = *reinterpret_cast<const float4*>(Xs + rl * 12);
            float4 v1 = *reinterpret_cast<const float4*>(Xs + rl * 12 + 4);
            af[rr][0] = v0.x; af[rr][1] = v0.y; af[rr][2] = v0.z; af[rr][3] = v0.w;
            af[rr][4] = v1.x; af[rr][5] = v1.y; af[rr][6] = v1.z; af[rr][7] = v1.w;
        }

#pragma unroll
        for (int k = 0; k < 8; k++) {
            unsigned long long bm[4];
#pragma unroll
            for (int rr = 0; rr < 4; rr++)
                asm("mov.b64 %0, {%1, %1};" : "=l"(bm[rr]) : "f"(af[rr][k]));
            uint32_t rowa = w_base + (uint32_t)(cc * 8 + k) * (NC * 4);
#pragma unroll
            for (int q = 0; q < 8; q++) {
                unsigned long long w0, w1;
                asm("ld.shared.v2.b64 {%0, %1}, [%2];"
                    : "=l"(w0), "=l"(w1) : "r"(rowa + q * 16));
#pragma unroll
                for (int rr = 0; rr < 4; rr++) {
                    asm("fma.rn.f32x2 %0, %1, %2, %0;" : "+l"(acc[rr][2*q])   : "l"(bm[rr]), "l"(w0));
                    asm("fma.rn.f32x2 %0, %1, %2, %0;" : "+l"(acc[rr][2*q+1]) : "l"(bm[rr]), "l"(w1));
                }
            }
        }
        __syncthreads();
    }

    // convert to fp16 and store (32 halves = 4x uint4 per row-part)
#pragma unroll
    for (int rr = 0; rr < 4; rr++) {
        int r = rbase + pair * 128 + 32 * rr + l;
        if (r >= NN) continue;
        uint4* yo = reinterpret_cast<uint4*>(
            reinterpret_cast<char*>(g_yh) + (size_t)r * (NC * 2) + ch * 64);
#pragma unroll
        for (int q = 0; q < 4; q++) {
            float2 f0, f1, f2, f3;
            asm("mov.b64 {%0, %1}, %2;" : "=f"(f0.x), "=f"(f0.y) : "l"(acc[rr][4*q]));
            asm("mov.b64 {%0, %1}, %2;" : "=f"(f1.x), "=f"(f1.y) : "l"(acc[rr][4*q+1]));
            asm("mov.b64 {%0, %1}, %2;" : "=f"(f2.x), "=f"(f2.y) : "l"(acc[rr][4*q+2]));
            asm("mov.b64 {%0, %1}, %2;" : "=f"(f3.x), "=f"(f3.y) : "l"(acc[rr][4*q+3]));
            uint4 o;
            o.x = h2_to_u32(__floats2half2_rn(f0.x, f0.y));
            o.y = h2_to_u32(__floats2half2_rn(f1.x, f1.y));
            o.z = h2_to_u32(__floats2half2_rn(f2.x, f2.y));
            o.w = h2_to_u32(__floats2half2_rn(f3.x, f3.y));
            yo[q] = o;
        }
    }
}

// ---------------------------------------------------------------------------
// 6) fused gather + log_softmax, warp per node, fp16 y (1 L2 line per edge).
// ---------------------------------------------------------------------------
__global__ __launch_bounds__(256) void gather_out_kernel(const float* __restrict__ b,
                                                         float* __restrict__ out) {
    int node = (blockIdx.x * 256 + threadIdx.x) >> 5;
    int l = threadIdx.x & 31;
    if (node >= NN) return;
    int half = l >> 4, chunk = l & 15;

    int start = g_rowstart[node];
    int n = g_cnt[node];
    float di = g_dinv[node];
    const uint2* y2p = reinterpret_cast<const uint2*>(g_yh);  // 8B = 4 halves

    float4 acc = make_float4(0.f, 0.f, 0.f, 0.f);
    if (half == 0) {   // self loop: y[node] * dinv[node]
        uint2 u = y2p[(size_t)node * 16 + chunk];
        float2 a = __half22float2(u32_to_h2(u.x));
        float2 c = __half22float2(u32_to_h2(u.y));
        acc.x = a.x * di; acc.y = a.y * di; acc.z = c.x * di; acc.w = c.y * di;
    }

    for (int base = 0; base < n; base += 32) {
        int idx = base + l;
        int s = 0; float dv = 0.f;
        if (idx < n) { s = g_ssrc[start + idx]; dv = g_dinv[s]; }  // coalesced + gather
        int m = n - base; if (m > 32) m = 32;
        int jmax = (m + 1) >> 1;
#pragma unroll 2
        for (int j = 0; j < jmax; j++) {
            int myj = 2 * j + half;                    // even -> half0, odd -> half1
            int sj = __shfl_sync(0xffffffffu, s, myj);
            float dj = __shfl_sync(0xffffffffu, dv, myj);
            if (myj < m) {
                uint2 u = y2p[(size_t)sj * 16 + chunk];
                float2 a = __half22float2(u32_to_h2(u.x));
                float2 c = __half22float2(u32_to_h2(u.y));
                acc.x += a.x * dj; acc.y += a.y * dj;
                acc.z += c.x * dj; acc.w += c.y * dj;
            }
        }
    }

    // merge half-warps
    acc.x += __shfl_xor_sync(0xffffffffu, acc.x, 16);
    acc.y += __shfl_xor_sync(0xffffffffu, acc.y, 16);
    acc.z += __shfl_xor_sync(0xffffffffu, acc.z, 16);
    acc.w += __shfl_xor_sync(0xffffffffu, acc.w, 16);

    // redistribute: lane l takes logits [2l, 2l+1] from chunk l>>1
    int srcl = l >> 1;
    float4 v;
    v.x = __shfl_sync(0xffffffffu, acc.x, srcl);
    v.y = __shfl_sync(0xffffffffu, acc.y, srcl);
    v.z = __shfl_sync(0xffffffffu, acc.z, srcl);
    v.w = __shfl_sync(0xffffffffu, acc.w, srcl);
    float2 mine = (l & 1) ? make_float2(v.z, v.w) : make_float2(v.x, v.y);

    const float2* b2 = reinterpret_cast<const float2*>(b);
    float2 bb = b2[l];
    float l0 = mine.x * di + bb.x;
    float l1 = mine.y * di + bb.y;

    float m = fmaxf(l0, l1);
#pragma unroll
    for (int o = 16; o; o >>= 1) m = fmaxf(m, __shfl_xor_sync(0xffffffffu, m, o));
    float s = __expf(l0 - m) + __expf(l1 - m);
#pragma unroll
    for (int o = 16; o; o >>= 1) s += __shfl_xor_sync(0xffffffffu, s, o);
    float lse = m + __logf(s);

    reinterpret_cast<float2*>(out + (size_t)node * NC)[l] = make_float2(l0 - lse, l1 - lse);
}

// ---------------------------------------------------------------------------
extern "C" void kernel_launch(void* const* d_in, const int* in_sizes, int n_in,
                              void* d_out, int out_size) {
    const float* x  = (const float*)d_in[0];
    const int*   ei = (const int*)d_in[1];
    const float* W  = (const float*)d_in[2];
    const float* b  = (const float*)d_in[3];
    float* out = (float*)d_out;

    const int* src = ei;        // edge_index[0]
    const int* dst = ei + NE;   // edge_index[1]

    // Lazy init (first call = harness correctness run, before graph capture)
    if (!g_side) {
        cudaStreamCreateWithFlags(&g_side, cudaStreamNonBlocking);
        cudaEventCreateWithFlags(&g_evFork, cudaEventDisableTiming);
        cudaEventCreateWithFlags(&g_evJoin, cudaEventDisableTiming);
    }

    // Fork: gemm on side stream (independent of edge chain)
    cudaEventRecord(g_evFork, 0);
    cudaStreamWaitEvent(g_side, g_evFork, 0);
    gemm3_kernel<<<(NN + 255) / 256, 128, 0, g_side>>>(x, W);
    cudaEventRecord(g_evJoin, g_side);

    // Edge chain on main stream
    zero_kernel<<<(NN + 255) / 256, 256>>>();
    hist_kernel<<<(NE + 255) / 256, 256>>>(dst);
    scan_a_kernel<<<SCAN_BLK, 1024>>>();
    scan_c_kernel<<<(NN + 255) / 256, 256>>>();
    scatter_kernel<<<(NE + 255) / 256, 256>>>(src, dst);

    // Join, then fused gather + softmax
    cudaStreamWaitEvent(0, g_evJoin, 0);
    gather_out_kernel<<<(NN * 32 + 255) / 256, 256>>>(b, out);
}